// round 14
// baseline (speedup 1.0000x reference)
#include <cuda_runtime.h>
#include <math_constants.h>

#define EPS_WH 1e-07f
#define MAX_WH 10000000.0f
#define THREADS 256

// Scratch: per-block argmax keys + completion counter.
__device__ unsigned long long g_keys[4096];
__device__ int g_count;       // zero-initialized; reset by last block each run

__device__ __forceinline__ float clip_wh(float v) {
    return fminf(fmaxf(v, EPS_WH), MAX_WH);
}

__device__ __forceinline__ unsigned int f2sortable(float f) {
    unsigned int u = __float_as_uint(f);
    return (u & 0x80000000u) ? ~u : (u | 0x80000000u);
}

__device__ __forceinline__ float gwd_loss_one(
    const float* __restrict__ ab, const float* __restrict__ trig,
    const float* __restrict__ center, const float* __restrict__ target,
    int b, int idx, int HW)
{
    const float* abb = ab   + (size_t)b * 2 * HW;
    const float* tgb = trig + (size_t)b * 2 * HW;
    float a1    = __ldg(&abb[idx]);
    float a2    = __ldg(&abb[HW + idx]);
    float sin2A = __ldg(&tgb[idx]);
    float cos2A = __ldg(&tgb[HW + idx]);

    // deg roundtrip in the reference is the identity; stay in radians
    float r_p = 0.5f * atan2f(sin2A, cos2A);
    float xp = center[2 * b], yp = center[2 * b + 1];
    float s1p = 0.5f * clip_wh(2.0f * a1);
    float s2p = 0.5f * clip_wh(2.0f * a2);
    float cp = cosf(r_p), sp = sinf(r_p);

    float xt = target[5 * b + 0];
    float yt = target[5 * b + 1];
    float s1t = 0.5f * clip_wh(target[5 * b + 2]);
    float s2t = 0.5f * clip_wh(target[5 * b + 3]);
    float r_t = target[5 * b + 4] * (CUDART_PI_F / 180.0f);
    float ct = cosf(r_t), st = sinf(r_t);

    float dx = xp - xt, dy = yp - yt;
    float xy_dist = dx * dx + dy * dy;

    float sp1_2 = s1p * s1p, sp2_2 = s2p * s2p;
    float st1_2 = s1t * s1t, st2_2 = s2t * s2t;

    float Ap = sp1_2 * cp * cp + sp2_2 * sp * sp;
    float Bp = sp1_2 * sp * sp + sp2_2 * cp * cp;
    float Cp = (sp1_2 - sp2_2) * cp * sp;

    float At = st1_2 * ct * ct + st2_2 * st * st;
    float Bt = st1_2 * st * st + st2_2 * ct * ct;
    float Ct = (st1_2 - st2_2) * ct * st;

    float tr_pt = Ap * At + Bp * Bt + 2.0f * Cp * Ct;
    float det_sqrt = sqrtf(fmaxf(s1p * s2p * s1t * s2t, 0.0f));

    float whr = sp1_2 + sp2_2 + st1_2 + st2_2
              - 2.0f * sqrtf(fmaxf(tr_pt + 2.0f * det_sqrt, 0.0f));

    float dist = fmaxf(xy_dist + whr, 0.0f);
    return 1.0f - 1.0f / (1.0f + dist);
}

// One block per batch row. Two independent (best, bidx) chains consuming two
// back-to-back PLAIN LDG.128s per iteration (no cache hints — the __ldcs
// variants consistently regressed). Guarantees 2 independent outstanding
// loads per warp and halves the serial FMNMX/SEL chain.
__global__ void __launch_bounds__(THREADS)
gwd_fused_kernel(const float* __restrict__ hm,
                 const float* __restrict__ ab,
                 const float* __restrict__ trig,
                 const float* __restrict__ center,
                 const float* __restrict__ target,
                 float* __restrict__ out,
                 int HW, int B)
{
    const int b = blockIdx.x;
    const int t = threadIdx.x;

    const float4* hm4 = reinterpret_cast<const float4*>(hm + (size_t)b * HW);
    const int n4 = HW >> 2;               // 4096 float4 per row
    const int STEP = 2 * THREADS;         // two quads per iteration

    float best0 = -CUDART_INF_F, best1 = -CUDART_INF_F;
    int bidx0 = 0, bidx1 = 0;

    #pragma unroll 4
    for (int i = t; i < n4; i += STEP) {
        // Two independent loads (default caching), issued back-to-back.
        float4 v0 = hm4[i];
        float4 v1 = hm4[i + THREADS];

        // Chain 0
        {
            int base = i << 2;
            float m = fmaxf(fmaxf(v0.x, v0.y), fmaxf(v0.z, v0.w));
            int idx4 = (v0.z == m) ? (base + 2) : (base + 3);
            idx4     = (v0.y == m) ? (base + 1) : idx4;
            idx4     = (v0.x == m) ?  base      : idx4;
            bidx0 = (m > best0) ? idx4 : bidx0;
            best0 = fmaxf(best0, m);
        }
        // Chain 1 (independent)
        {
            int base = (i + THREADS) << 2;
            float m = fmaxf(fmaxf(v1.x, v1.y), fmaxf(v1.z, v1.w));
            int idx4 = (v1.z == m) ? (base + 2) : (base + 3);
            idx4     = (v1.y == m) ? (base + 1) : idx4;
            idx4     = (v1.x == m) ?  base      : idx4;
            bidx1 = (m > best1) ? idx4 : bidx1;
            best1 = fmaxf(best1, m);
        }
    }

    // Merge the two chains via packed keys (ties -> smaller index, which
    // preserves exact first-occurrence semantics).
    unsigned long long key0 =
        ((unsigned long long)f2sortable(best0) << 32) |
        (unsigned long long)(unsigned int)(~bidx0);
    unsigned long long key1 =
        ((unsigned long long)f2sortable(best1) << 32) |
        (unsigned long long)(unsigned int)(~bidx1);
    unsigned long long key = (key1 > key0) ? key1 : key0;

    #pragma unroll
    for (int off = 16; off > 0; off >>= 1) {
        unsigned long long o = __shfl_xor_sync(0xffffffffu, key, off);
        key = (o > key) ? o : key;
    }

    __shared__ unsigned long long skey[THREADS / 32];
    if ((t & 31) == 0) skey[t >> 5] = key;
    __syncthreads();
    if (t < 32) {
        unsigned long long k = (t < THREADS / 32) ? skey[t] : 0ull;
        #pragma unroll
        for (int off = 4; off > 0; off >>= 1) {
            unsigned long long o = __shfl_xor_sync(0xffffffffu, k, off);
            k = (o > k) ? o : k;
        }
        if (t == 0) g_keys[b] = k;
    }

    // ---- last-block-done: all epilogues + deterministic mean ----
    __shared__ bool amLast;
    __syncthreads();
    if (t == 0) {
        __threadfence();
        amLast = (atomicAdd(&g_count, 1) == gridDim.x - 1);
    }
    __syncthreads();

    if (amLast) {
        __threadfence();  // make peer g_keys writes visible

        float acc = 0.0f;
        for (int bb = t; bb < B; bb += THREADS) {
            unsigned long long kk = __ldcg(&g_keys[bb]);
            int idx = (int)(~((unsigned int)(kk & 0xffffffffu)));
            acc += gwd_loss_one(ab, trig, center, target, bb, idx, HW);
        }

        __shared__ float sh[THREADS];
        sh[t] = acc;
        __syncthreads();
        #pragma unroll
        for (int s = THREADS / 2; s > 0; s >>= 1) {
            if (t < s) sh[t] += sh[t + s];
            __syncthreads();
        }
        if (t == 0) {
            out[0] = sh[0] / (float)B;
            g_count = 0;  // reset for next graph replay
        }
    }
}

extern "C" void kernel_launch(void* const* d_in, const int* in_sizes, int n_in,
                              void* d_out, int out_size)
{
    const float* hm     = (const float*)d_in[0];  // (B,1,H,W)
    const float* ab     = (const float*)d_in[1];  // (B,2,H,W)
    const float* trig   = (const float*)d_in[2];  // (B,2,H,W)
    const float* center = (const float*)d_in[3];  // (B,2)
    const float* target = (const float*)d_in[4];  // (B,5)
    float* out = (float*)d_out;

    const int B  = in_sizes[4] / 5;
    const int HW = in_sizes[0] / B;   // 16384

    gwd_fused_kernel<<<B, THREADS>>>(hm, ab, trig, center, target, out, HW, B);
}

// round 15
// speedup vs baseline: 1.2662x; 1.2662x over previous
#include <cuda_runtime.h>
#include <math_constants.h>

#define EPS_WH 1e-07f
#define MAX_WH 10000000.0f
#define THREADS 256

// Per-batch partial losses + completion counter.
__device__ float g_partial[4096];
__device__ int   g_count;   // zero-initialized; reset by last block each run

__device__ __forceinline__ float clip_wh(float v) {
    return fminf(fmaxf(v, EPS_WH), MAX_WH);
}

// Map float bits to a monotonically ordered uint32 (standard sortable trick).
__device__ __forceinline__ unsigned int f2sortable(float f) {
    unsigned int u = __float_as_uint(f);
    return (u & 0x80000000u) ? ~u : (u | 0x80000000u);
}

// One block per batch element: branchless argmax over HW heatmap values,
// gather 4 floats, closed-form GWD loss. Last block does the deterministic mean.
__global__ void __launch_bounds__(THREADS)
gwd_fused_kernel(const float* __restrict__ hm,
                 const float* __restrict__ ab,
                 const float* __restrict__ trig,
                 const float* __restrict__ center,
                 const float* __restrict__ target,
                 float* __restrict__ out,
                 int HW, int B)
{
    const int b = blockIdx.x;
    const int t = threadIdx.x;

    // ---- argmax over hm[b, 0, :] (sigmoid is monotone -> same argmax) ----
    const float4* hm4 = reinterpret_cast<const float4*>(hm + (size_t)b * HW);
    const int n4 = HW >> 2;

    float best = -CUDART_INF_F;
    int bidx = 0;

    // Branchless: per float4, FMNMX tree for lane max, SEL chain for the
    // first-occurrence intra-quad index, one FMNMX + one SEL carried chain.
    // Trip count is 16 for this problem; full unroll removes loop overhead.
    #pragma unroll 16
    for (int i = t; i < n4; i += THREADS) {
        float4 v = hm4[i];
        int base = i << 2;

        float m = fmaxf(fmaxf(v.x, v.y), fmaxf(v.z, v.w));

        int idx4 = (v.z == m) ? (base + 2) : (base + 3);
        idx4     = (v.y == m) ? (base + 1) : idx4;
        idx4     = (v.x == m) ?  base      : idx4;

        bidx = (m > best) ? idx4 : bidx;   // strict > keeps earliest i on ties
        best = fmaxf(best, m);
    }

    // Pack (sortable value | ~idx): max over this picks max value, and on
    // value ties the smallest index (matching jnp.argmax first-occurrence).
    unsigned long long key =
        ((unsigned long long)f2sortable(best) << 32) |
        (unsigned long long)(unsigned int)(~bidx);

    // warp reduce
    #pragma unroll
    for (int off = 16; off > 0; off >>= 1) {
        unsigned long long o = __shfl_xor_sync(0xffffffffu, key, off);
        key = (o > key) ? o : key;
    }

    __shared__ unsigned long long skey[THREADS / 32];
    if ((t & 31) == 0) skey[t >> 5] = key;
    __syncthreads();
    if (t < 32) {
        unsigned long long k = (t < THREADS / 32) ? skey[t] : 0ull;
        #pragma unroll
        for (int off = 4; off > 0; off >>= 1) {
            unsigned long long o = __shfl_xor_sync(0xffffffffu, k, off);
            k = (o > k) ? o : k;
        }
        if (t == 0) skey[0] = k;
    }
    __syncthreads();

    if (t == 0) {
        const int idx = (int)(~((unsigned int)(skey[0] & 0xffffffffu)));

        // ---- gather (4 scattered loads instead of streaming 268 MB) ----
        const float* abb = ab   + (size_t)b * 2 * HW;
        const float* tgb = trig + (size_t)b * 2 * HW;
        float a1    = abb[idx];
        float a2    = abb[HW + idx];
        float sin2A = tgb[idx];
        float cos2A = tgb[HW + idx];

        // pred box: deg roundtrip in the reference is identity, keep radians
        float r_p = 0.5f * atan2f(sin2A, cos2A);
        float xp = center[2 * b], yp = center[2 * b + 1];
        float wp = clip_wh(2.0f * a1);
        float hp = clip_wh(2.0f * a2);
        float s1p = 0.5f * wp, s2p = 0.5f * hp;
        float cp = cosf(r_p), sp = sinf(r_p);

        // target box
        float xt = target[5 * b + 0];
        float yt = target[5 * b + 1];
        float wt = clip_wh(target[5 * b + 2]);
        float ht = clip_wh(target[5 * b + 3]);
        float r_t = target[5 * b + 4] * (CUDART_PI_F / 180.0f);
        float s1t = 0.5f * wt, s2t = 0.5f * ht;
        float ct = cosf(r_t), st = sinf(r_t);

        float dx = xp - xt, dy = yp - yt;
        float xy_dist = dx * dx + dy * dy;

        // Sigma = R diag(s^2) R^T for 2x2: closed form
        float sp1_2 = s1p * s1p, sp2_2 = s2p * s2p;
        float st1_2 = s1t * s1t, st2_2 = s2t * s2t;

        float Ap = sp1_2 * cp * cp + sp2_2 * sp * sp;
        float Bp = sp1_2 * sp * sp + sp2_2 * cp * cp;
        float Cp = (sp1_2 - sp2_2) * cp * sp;

        float At = st1_2 * ct * ct + st2_2 * st * st;
        float Bt = st1_2 * st * st + st2_2 * ct * ct;
        float Ct = (st1_2 - st2_2) * ct * st;

        float tr_pt = Ap * At + Bp * Bt + 2.0f * Cp * Ct;
        float det_sqrt = sqrtf(fmaxf(s1p * s2p * s1t * s2t, 0.0f));

        float whr = sp1_2 + sp2_2 + st1_2 + st2_2
                  - 2.0f * sqrtf(fmaxf(tr_pt + 2.0f * det_sqrt, 0.0f));

        float dist = fmaxf(xy_dist + whr, 0.0f);
        float loss = 1.0f - 1.0f / (1.0f + dist);
        g_partial[b] = loss;
    }
    __syncthreads();

    // ---- last-block-done: deterministic mean over all partials ----
    __shared__ bool amLast;
    if (t == 0) {
        __threadfence();
        amLast = (atomicAdd(&g_count, 1) == gridDim.x - 1);
    }
    __syncthreads();

    if (amLast) {
        float acc = 0.0f;
        // Fixed order per thread, single block: bitwise deterministic.
        for (int i = t; i < B; i += THREADS) acc += __ldcg(&g_partial[i]);

        __shared__ float sh[THREADS];
        sh[t] = acc;
        __syncthreads();
        #pragma unroll
        for (int s = THREADS / 2; s > 0; s >>= 1) {
            if (t < s) sh[t] += sh[t + s];
            __syncthreads();
        }
        if (t == 0) {
            out[0] = sh[0] / (float)B;
            g_count = 0;  // reset for next graph replay
        }
    }
}

extern "C" void kernel_launch(void* const* d_in, const int* in_sizes, int n_in,
                              void* d_out, int out_size)
{
    const float* hm     = (const float*)d_in[0];  // (B,1,H,W)
    const float* ab     = (const float*)d_in[1];  // (B,2,H,W)
    const float* trig   = (const float*)d_in[2];  // (B,2,H,W)
    const float* center = (const float*)d_in[3];  // (B,2)
    const float* target = (const float*)d_in[4];  // (B,5)
    float* out = (float*)d_out;

    const int B  = in_sizes[4] / 5;
    const int HW = in_sizes[0] / B;

    gwd_fused_kernel<<<B, THREADS>>>(hm, ab, trig, center, target, out, HW, B);
}

// round 16
// speedup vs baseline: 1.3233x; 1.0451x over previous
#include <cuda_runtime.h>
#include <math_constants.h>

#define EPS_WH 1e-07f
#define MAX_WH 10000000.0f
#define THREADS 256

// Per-batch partial losses + completion counter.
__device__ float g_partial[4096];
__device__ int   g_count;   // zero-initialized; reset by last block each run

__device__ __forceinline__ float clip_wh(float v) {
    return fminf(fmaxf(v, EPS_WH), MAX_WH);
}

// Map float bits to a monotonically ordered uint32 (standard sortable trick).
__device__ __forceinline__ unsigned int f2sortable(float f) {
    unsigned int u = __float_as_uint(f);
    return (u & 0x80000000u) ? ~u : (u | 0x80000000u);
}

// One block per batch element: branchless argmax over HW heatmap values,
// gather 4 floats, closed-form GWD loss. Last block does the deterministic mean.
// Configuration locked from the best measured round (12.80 us):
//   256 threads, 1024 blocks, plain strided float4 loads, unroll 8.
__global__ void __launch_bounds__(THREADS)
gwd_fused_kernel(const float* __restrict__ hm,
                 const float* __restrict__ ab,
                 const float* __restrict__ trig,
                 const float* __restrict__ center,
                 const float* __restrict__ target,
                 float* __restrict__ out,
                 int HW, int B)
{
    const int b = blockIdx.x;
    const int t = threadIdx.x;

    // ---- argmax over hm[b, 0, :] (sigmoid is monotone -> same argmax) ----
    const float4* hm4 = reinterpret_cast<const float4*>(hm + (size_t)b * HW);
    const int n4 = HW >> 2;

    float best = -CUDART_INF_F;
    int bidx = 0;

    // Branchless: per float4, FMNMX tree for lane max, SEL chain for the
    // first-occurrence intra-quad index, one FMNMX + one SEL carried chain.
    // unroll 8 is the measured sweet spot (16 inflates L1tex-queue spread).
    #pragma unroll 8
    for (int i = t; i < n4; i += THREADS) {
        float4 v = hm4[i];
        int base = i << 2;

        float m = fmaxf(fmaxf(v.x, v.y), fmaxf(v.z, v.w));

        int idx4 = (v.z == m) ? (base + 2) : (base + 3);
        idx4     = (v.y == m) ? (base + 1) : idx4;
        idx4     = (v.x == m) ?  base      : idx4;

        bidx = (m > best) ? idx4 : bidx;   // strict > keeps earliest i on ties
        best = fmaxf(best, m);
    }

    // Pack (sortable value | ~idx): max over this picks max value, and on
    // value ties the smallest index (matching jnp.argmax first-occurrence).
    unsigned long long key =
        ((unsigned long long)f2sortable(best) << 32) |
        (unsigned long long)(unsigned int)(~bidx);

    // warp reduce
    #pragma unroll
    for (int off = 16; off > 0; off >>= 1) {
        unsigned long long o = __shfl_xor_sync(0xffffffffu, key, off);
        key = (o > key) ? o : key;
    }

    __shared__ unsigned long long skey[THREADS / 32];
    if ((t & 31) == 0) skey[t >> 5] = key;
    __syncthreads();
    if (t < 32) {
        unsigned long long k = (t < THREADS / 32) ? skey[t] : 0ull;
        #pragma unroll
        for (int off = 16; off > 0; off >>= 1) {
            unsigned long long o = __shfl_xor_sync(0xffffffffu, k, off);
            k = (o > k) ? o : k;
        }
        if (t == 0) skey[0] = k;
    }
    __syncthreads();

    if (t == 0) {
        const int idx = (int)(~((unsigned int)(skey[0] & 0xffffffffu)));

        // ---- gather (4 scattered loads instead of streaming 268 MB) ----
        const float* abb = ab   + (size_t)b * 2 * HW;
        const float* tgb = trig + (size_t)b * 2 * HW;
        float a1    = abb[idx];
        float a2    = abb[HW + idx];
        float sin2A = tgb[idx];
        float cos2A = tgb[HW + idx];

        // pred box: deg roundtrip in the reference is identity, keep radians
        float r_p = 0.5f * atan2f(sin2A, cos2A);
        float xp = center[2 * b], yp = center[2 * b + 1];
        float wp = clip_wh(2.0f * a1);
        float hp = clip_wh(2.0f * a2);
        float s1p = 0.5f * wp, s2p = 0.5f * hp;
        float cp = cosf(r_p), sp = sinf(r_p);

        // target box
        float xt = target[5 * b + 0];
        float yt = target[5 * b + 1];
        float wt = clip_wh(target[5 * b + 2]);
        float ht = clip_wh(target[5 * b + 3]);
        float r_t = target[5 * b + 4] * (CUDART_PI_F / 180.0f);
        float s1t = 0.5f * wt, s2t = 0.5f * ht;
        float ct = cosf(r_t), st = sinf(r_t);

        float dx = xp - xt, dy = yp - yt;
        float xy_dist = dx * dx + dy * dy;

        // Sigma = R diag(s^2) R^T for 2x2: closed form
        float sp1_2 = s1p * s1p, sp2_2 = s2p * s2p;
        float st1_2 = s1t * s1t, st2_2 = s2t * s2t;

        float Ap = sp1_2 * cp * cp + sp2_2 * sp * sp;
        float Bp = sp1_2 * sp * sp + sp2_2 * cp * cp;
        float Cp = (sp1_2 - sp2_2) * cp * sp;

        float At = st1_2 * ct * ct + st2_2 * st * st;
        float Bt = st1_2 * st * st + st2_2 * ct * ct;
        float Ct = (st1_2 - st2_2) * ct * st;

        float tr_pt = Ap * At + Bp * Bt + 2.0f * Cp * Ct;
        float det_sqrt = sqrtf(fmaxf(s1p * s2p * s1t * s2t, 0.0f));

        float whr = sp1_2 + sp2_2 + st1_2 + st2_2
                  - 2.0f * sqrtf(fmaxf(tr_pt + 2.0f * det_sqrt, 0.0f));

        float dist = fmaxf(xy_dist + whr, 0.0f);
        float loss = 1.0f - 1.0f / (1.0f + dist);
        g_partial[b] = loss;
    }
    __syncthreads();

    // ---- last-block-done: deterministic mean over all partials ----
    __shared__ bool amLast;
    if (t == 0) {
        __threadfence();
        amLast = (atomicAdd(&g_count, 1) == gridDim.x - 1);
    }
    __syncthreads();

    if (amLast) {
        float acc = 0.0f;
        // Fixed order per thread, single block: bitwise deterministic.
        // __ldcg: bypass L1 (partials were written by other SMs).
        for (int i = t; i < B; i += THREADS) acc += __ldcg(&g_partial[i]);

        __shared__ float sh[THREADS];
        sh[t] = acc;
        __syncthreads();
        #pragma unroll
        for (int s = THREADS / 2; s > 0; s >>= 1) {
            if (t < s) sh[t] += sh[t + s];
            __syncthreads();
        }
        if (t == 0) {
            out[0] = sh[0] / (float)B;
            g_count = 0;  // reset for next graph replay
        }
    }
}

extern "C" void kernel_launch(void* const* d_in, const int* in_sizes, int n_in,
                              void* d_out, int out_size)
{
    const float* hm     = (const float*)d_in[0];  // (B,1,H,W)
    const float* ab     = (const float*)d_in[1];  // (B,2,H,W)
    const float* trig   = (const float*)d_in[2];  // (B,2,H,W)
    const float* center = (const float*)d_in[3];  // (B,2)
    const float* target = (const float*)d_in[4];  // (B,5)
    float* out = (float*)d_out;

    const int B  = in_sizes[4] / 5;
    const int HW = in_sizes[0] / B;

    gwd_fused_kernel<<<B, THREADS>>>(hm, ab, trig, center, target, out, HW, B);
}

// round 17
// speedup vs baseline: 1.3504x; 1.0205x over previous
#include <cuda_runtime.h>
#include <math_constants.h>

#define EPS_WH 1e-07f
#define MAX_WH 10000000.0f
#define THREADS 128

// Per-batch partial losses + completion counter.
__device__ float g_partial[4096];
__device__ int   g_count;   // zero-initialized; reset by last block each run

__device__ __forceinline__ float clip_wh(float v) {
    return fminf(fmaxf(v, EPS_WH), MAX_WH);
}

// Map float bits to a monotonically ordered uint32 (standard sortable trick).
__device__ __forceinline__ unsigned int f2sortable(float f) {
    unsigned int u = __float_as_uint(f);
    return (u & 0x80000000u) ? ~u : (u | 0x80000000u);
}

// One block (128 threads) per batch element: 16 CTAs/SM at regs=32 -> more
// independently progressing load streams per SM than the 256-thread shape,
// narrower barrier ladders, smaller epilogue park. Same per-element code.
__global__ void __launch_bounds__(THREADS)
gwd_fused_kernel(const float* __restrict__ hm,
                 const float* __restrict__ ab,
                 const float* __restrict__ trig,
                 const float* __restrict__ center,
                 const float* __restrict__ target,
                 float* __restrict__ out,
                 int HW, int B)
{
    const int b = blockIdx.x;
    const int t = threadIdx.x;

    // ---- argmax over hm[b, 0, :] (sigmoid is monotone -> same argmax) ----
    const float4* hm4 = reinterpret_cast<const float4*>(hm + (size_t)b * HW);
    const int n4 = HW >> 2;

    float best = -CUDART_INF_F;
    int bidx = 0;

    // Branchless: per float4, FMNMX tree for lane max, SEL chain for the
    // first-occurrence intra-quad index, one FMNMX + one SEL carried chain.
    // unroll 8 is the measured sweet spot.
    #pragma unroll 8
    for (int i = t; i < n4; i += THREADS) {
        float4 v = hm4[i];
        int base = i << 2;

        float m = fmaxf(fmaxf(v.x, v.y), fmaxf(v.z, v.w));

        int idx4 = (v.z == m) ? (base + 2) : (base + 3);
        idx4     = (v.y == m) ? (base + 1) : idx4;
        idx4     = (v.x == m) ?  base      : idx4;

        bidx = (m > best) ? idx4 : bidx;   // strict > keeps earliest i on ties
        best = fmaxf(best, m);
    }

    // Pack (sortable value | ~idx): max over this picks max value, and on
    // value ties the smallest index (matching jnp.argmax first-occurrence).
    unsigned long long key =
        ((unsigned long long)f2sortable(best) << 32) |
        (unsigned long long)(unsigned int)(~bidx);

    // warp reduce
    #pragma unroll
    for (int off = 16; off > 0; off >>= 1) {
        unsigned long long o = __shfl_xor_sync(0xffffffffu, key, off);
        key = (o > key) ? o : key;
    }

    __shared__ unsigned long long skey[THREADS / 32];   // 4 warps
    if ((t & 31) == 0) skey[t >> 5] = key;
    __syncthreads();
    if (t < 32) {
        unsigned long long k = (t < THREADS / 32) ? skey[t] : 0ull;
        #pragma unroll
        for (int off = 2; off > 0; off >>= 1) {
            unsigned long long o = __shfl_xor_sync(0xffffffffu, k, off);
            k = (o > k) ? o : k;
        }
        if (t == 0) skey[0] = k;
    }
    __syncthreads();

    if (t == 0) {
        const int idx = (int)(~((unsigned int)(skey[0] & 0xffffffffu)));

        // ---- gather (4 scattered loads instead of streaming 268 MB) ----
        const float* abb = ab   + (size_t)b * 2 * HW;
        const float* tgb = trig + (size_t)b * 2 * HW;
        float a1    = abb[idx];
        float a2    = abb[HW + idx];
        float sin2A = tgb[idx];
        float cos2A = tgb[HW + idx];

        // pred box: deg roundtrip in the reference is identity, keep radians
        float r_p = 0.5f * atan2f(sin2A, cos2A);
        float xp = center[2 * b], yp = center[2 * b + 1];
        float wp = clip_wh(2.0f * a1);
        float hp = clip_wh(2.0f * a2);
        float s1p = 0.5f * wp, s2p = 0.5f * hp;
        float cp = cosf(r_p), sp = sinf(r_p);

        // target box
        float xt = target[5 * b + 0];
        float yt = target[5 * b + 1];
        float wt = clip_wh(target[5 * b + 2]);
        float ht = clip_wh(target[5 * b + 3]);
        float r_t = target[5 * b + 4] * (CUDART_PI_F / 180.0f);
        float s1t = 0.5f * wt, s2t = 0.5f * ht;
        float ct = cosf(r_t), st = sinf(r_t);

        float dx = xp - xt, dy = yp - yt;
        float xy_dist = dx * dx + dy * dy;

        // Sigma = R diag(s^2) R^T for 2x2: closed form
        float sp1_2 = s1p * s1p, sp2_2 = s2p * s2p;
        float st1_2 = s1t * s1t, st2_2 = s2t * s2t;

        float Ap = sp1_2 * cp * cp + sp2_2 * sp * sp;
        float Bp = sp1_2 * sp * sp + sp2_2 * cp * cp;
        float Cp = (sp1_2 - sp2_2) * cp * sp;

        float At = st1_2 * ct * ct + st2_2 * st * st;
        float Bt = st1_2 * st * st + st2_2 * ct * ct;
        float Ct = (st1_2 - st2_2) * ct * st;

        float tr_pt = Ap * At + Bp * Bt + 2.0f * Cp * Ct;
        float det_sqrt = sqrtf(fmaxf(s1p * s2p * s1t * s2t, 0.0f));

        float whr = sp1_2 + sp2_2 + st1_2 + st2_2
                  - 2.0f * sqrtf(fmaxf(tr_pt + 2.0f * det_sqrt, 0.0f));

        float dist = fmaxf(xy_dist + whr, 0.0f);
        float loss = 1.0f - 1.0f / (1.0f + dist);
        g_partial[b] = loss;
    }
    __syncthreads();

    // ---- last-block-done: deterministic mean over all partials ----
    __shared__ bool amLast;
    if (t == 0) {
        __threadfence();
        amLast = (atomicAdd(&g_count, 1) == gridDim.x - 1);
    }
    __syncthreads();

    if (amLast) {
        float acc = 0.0f;
        // Fixed order per thread, single block: bitwise deterministic.
        // __ldcg: bypass L1 (partials were written by other SMs).
        for (int i = t; i < B; i += THREADS) acc += __ldcg(&g_partial[i]);

        __shared__ float sh[THREADS];
        sh[t] = acc;
        __syncthreads();
        #pragma unroll
        for (int s = THREADS / 2; s > 0; s >>= 1) {
            if (t < s) sh[t] += sh[t + s];
            __syncthreads();
        }
        if (t == 0) {
            out[0] = sh[0] / (float)B;
            g_count = 0;  // reset for next graph replay
        }
    }
}

extern "C" void kernel_launch(void* const* d_in, const int* in_sizes, int n_in,
                              void* d_out, int out_size)
{
    const float* hm     = (const float*)d_in[0];  // (B,1,H,W)
    const float* ab     = (const float*)d_in[1];  // (B,2,H,W)
    const float* trig   = (const float*)d_in[2];  // (B,2,H,W)
    const float* center = (const float*)d_in[3];  // (B,2)
    const float* target = (const float*)d_in[4];  // (B,5)
    float* out = (float*)d_out;

    const int B  = in_sizes[4] / 5;
    const int HW = in_sizes[0] / B;

    gwd_fused_kernel<<<B, THREADS>>>(hm, ab, trig, center, target, out, HW, B);
}